// round 3
// baseline (speedup 1.0000x reference)
#include <cuda_runtime.h>
#include <math.h>

#define N_MAX 1000000

// ---------------- device scratch (no allocation allowed) ----------------
static __device__ float    g_deg[N_MAX];     // weighted in-degree per node
static __device__ float    g_dinv[N_MAX];    // rsqrt(deg)
static __device__ float4   g_x[N_MAX];       // emb@w_conv, later conv1 output (padded)
static __device__ float4   g_agg[N_MAX];     // message accumulator (padded for v4 red)
static __device__ unsigned g_maxu[3];        // column max (order-preserving uint key)
static __device__ float    g_sum[3];         // column sum of exp(h - max)
static __device__ float    g_lse[3];         // final logsumexp per column

// packed weights: [0:9) w_conv, [9:12) b_conv, [12:48) w1, [48:54) b1,
//                 [54:72) w3, [72:75) b3
static __device__ float g_w[80];

__device__ __forceinline__ float lrelu(float x) { return x >= 0.f ? x : 0.01f * x; }

// order-preserving float->uint key for atomicMax over signed floats
__device__ __forceinline__ unsigned fkey(float x) {
    unsigned u = __float_as_uint(x);
    return (u & 0x80000000u) ? ~u : (u | 0x80000000u);
}
__device__ __forceinline__ float funkey(unsigned k) {
    return __uint_as_float((k & 0x80000000u) ? (k ^ 0x80000000u) : ~k);
}

// ---------------- kernels ----------------

// copy all weight tensors into one __device__ array; reset reduction scalars
__global__ void k_weights(const float* __restrict__ wconv, const float* __restrict__ bconv,
                          const float* __restrict__ w1, const float* __restrict__ b1,
                          const float* __restrict__ w3, const float* __restrict__ b3) {
    int t = threadIdx.x;
    if (t < 9)  g_w[t]      = wconv[t];
    if (t < 3)  g_w[9 + t]  = bconv[t];
    if (t < 36) g_w[12 + t] = w1[t];
    if (t < 6)  g_w[48 + t] = b1[t];
    if (t < 18) g_w[54 + t] = w3[t];
    if (t < 3)  g_w[72 + t] = b3[t];
    if (t < 3)  { g_maxu[t] = 0u; g_sum[t] = 0.f; }
}

// init: zero accumulators, transform features x = emb @ w_conv
__global__ void k_init(const float* __restrict__ emb, int n) {
    int i = blockIdx.x * blockDim.x + threadIdx.x;
    if (i < n) {
        float e0 = emb[3 * i + 0];
        float e1 = emb[3 * i + 1];
        float e2 = emb[3 * i + 2];
        float4 x;
        x.x = e0 * g_w[0] + e1 * g_w[3] + e2 * g_w[6];
        x.y = e0 * g_w[1] + e1 * g_w[4] + e2 * g_w[7];
        x.z = e0 * g_w[2] + e1 * g_w[5] + e2 * g_w[8];
        x.w = 0.f;
        g_x[i] = x;
        g_deg[i] = 0.f;
        g_agg[i] = make_float4(0.f, 0.f, 0.f, 0.f);
    }
}

// weighted in-degree over target nodes (col)
__global__ void k_deg(const int* __restrict__ col, const float* __restrict__ ew, int e) {
    int i = blockIdx.x * blockDim.x + threadIdx.x;
    if (i < e) {
        atomicAdd(&g_deg[__ldg(&col[i])], __ldg(&ew[i]));
    }
}

__global__ void k_dinv(int n) {
    int i = blockIdx.x * blockDim.x + threadIdx.x;
    if (i < n) {
        float d = g_deg[i];
        g_dinv[i] = d > 0.f ? rsqrtf(d) : 0.f;
    }
}

// message pass: agg[col] += dinv[row]*ew*dinv[col] * x[row]  (single v4 reduction)
__global__ void k_msg(const int* __restrict__ row, const int* __restrict__ col,
                      const float* __restrict__ ew, int e) {
    int i = blockIdx.x * blockDim.x + threadIdx.x;
    if (i < e) {
        int r = __ldg(&row[i]);
        int c = __ldg(&col[i]);
        float nrm = g_dinv[r] * __ldg(&ew[i]) * g_dinv[c];
        float4 xv = g_x[r];
        float m0 = nrm * xv.x, m1 = nrm * xv.y, m2 = nrm * xv.z;
        float* p = reinterpret_cast<float*>(&g_agg[c]);
        asm volatile("red.global.add.v4.f32 [%0], {%1, %2, %3, %4};"
                     :: "l"(p), "f"(m0), "f"(m1), "f"(m2), "f"(0.f)
                     : "memory");
    }
}

// conv1 output: x = leaky_relu(agg + b_conv)
__global__ void k_node(int n) {
    int i = blockIdx.x * blockDim.x + threadIdx.x;
    if (i < n) {
        float4 a = g_agg[i];
        float4 o;
        o.x = lrelu(a.x + g_w[9]);
        o.y = lrelu(a.y + g_w[10]);
        o.z = lrelu(a.z + g_w[11]);
        o.w = 0.f;
        g_x[i] = o;
    }
}

// MLP per batch element + per-block column-max reduction
#define MLP_ITEMS 4
__global__ void k_mlp(const int* __restrict__ home, const int* __restrict__ away,
                      float* __restrict__ out, int b) {
    // stage weights in shared (warp-uniform broadcast reads afterwards)
    __shared__ float w[80];
    if (threadIdx.x < 80) w[threadIdx.x] = g_w[threadIdx.x];
    __syncthreads();

    int base = (blockIdx.x * blockDim.x + threadIdx.x) * MLP_ITEMS;
    float m0 = -INFINITY, m1 = -INFINITY, m2 = -INFINITY;
    #pragma unroll
    for (int t = 0; t < MLP_ITEMS; t++) {
        int idx = base + t;
        if (idx < b) {
            float4 xh = g_x[__ldg(&home[idx])];
            float4 xa = g_x[__ldg(&away[idx])];
            float h[6] = {xh.x, xh.y, xh.z, xa.x, xa.y, xa.z};
            float u[6];
            #pragma unroll
            for (int j = 0; j < 6; j++) {
                float s = w[48 + j];
                #pragma unroll
                for (int i2 = 0; i2 < 6; i2++) s += h[i2] * w[12 + i2 * 6 + j];
                u[j] = lrelu(s);
            }
            float o[3];
            #pragma unroll
            for (int j = 0; j < 3; j++) {
                float s = w[72 + j];
                #pragma unroll
                for (int i2 = 0; i2 < 6; i2++) s += u[i2] * w[54 + i2 * 3 + j];
                o[j] = lrelu(s);
            }
            out[3 * idx + 0] = o[0];
            out[3 * idx + 1] = o[1];
            out[3 * idx + 2] = o[2];
            m0 = fmaxf(m0, o[0]);
            m1 = fmaxf(m1, o[1]);
            m2 = fmaxf(m2, o[2]);
        }
    }
    // warp reduce
    #pragma unroll
    for (int off = 16; off; off >>= 1) {
        m0 = fmaxf(m0, __shfl_xor_sync(0xFFFFFFFFu, m0, off));
        m1 = fmaxf(m1, __shfl_xor_sync(0xFFFFFFFFu, m1, off));
        m2 = fmaxf(m2, __shfl_xor_sync(0xFFFFFFFFu, m2, off));
    }
    __shared__ float sm[3][8];
    int lane = threadIdx.x & 31, wpw = threadIdx.x >> 5;
    if (lane == 0) { sm[0][wpw] = m0; sm[1][wpw] = m1; sm[2][wpw] = m2; }
    __syncthreads();
    if (threadIdx.x < 3) {
        float m = sm[threadIdx.x][0];
        #pragma unroll
        for (int k = 1; k < 8; k++) m = fmaxf(m, sm[threadIdx.x][k]);
        atomicMax(&g_maxu[threadIdx.x], fkey(m));
    }
}

// column sums of exp(h - max)
__global__ void k_sum(const float* __restrict__ out, int b) {
    float M0 = funkey(g_maxu[0]);
    float M1 = funkey(g_maxu[1]);
    float M2 = funkey(g_maxu[2]);
    int base = (blockIdx.x * blockDim.x + threadIdx.x) * MLP_ITEMS;
    float s0 = 0.f, s1 = 0.f, s2 = 0.f;
    #pragma unroll
    for (int t = 0; t < MLP_ITEMS; t++) {
        int idx = base + t;
        if (idx < b) {
            s0 += __expf(out[3 * idx + 0] - M0);
            s1 += __expf(out[3 * idx + 1] - M1);
            s2 += __expf(out[3 * idx + 2] - M2);
        }
    }
    #pragma unroll
    for (int off = 16; off; off >>= 1) {
        s0 += __shfl_xor_sync(0xFFFFFFFFu, s0, off);
        s1 += __shfl_xor_sync(0xFFFFFFFFu, s1, off);
        s2 += __shfl_xor_sync(0xFFFFFFFFu, s2, off);
    }
    __shared__ float sm[3][8];
    int lane = threadIdx.x & 31, w = threadIdx.x >> 5;
    if (lane == 0) { sm[0][w] = s0; sm[1][w] = s1; sm[2][w] = s2; }
    __syncthreads();
    if (threadIdx.x < 3) {
        float s = 0.f;
        #pragma unroll
        for (int k = 0; k < 8; k++) s += sm[threadIdx.x][k];
        atomicAdd(&g_sum[threadIdx.x], s);
    }
}

__global__ void k_lse() {
    int c = threadIdx.x;
    if (c < 3) g_lse[c] = funkey(g_maxu[c]) + logf(g_sum[c]);
}

// out -= lse[col]
__global__ void k_final(float* __restrict__ out, int total) {
    int i = blockIdx.x * blockDim.x + threadIdx.x;
    if (i < total) {
        int c = i - (i / 3) * 3;
        out[i] -= g_lse[c];
    }
}

// ---------------- launch ----------------
extern "C" void kernel_launch(void* const* d_in, const int* in_sizes, int n_in,
                              void* d_out, int out_size) {
    const int*   edge_index = (const int*)d_in[0];   // [2, E]
    const float* ew         = (const float*)d_in[1]; // [E]
    const int*   home       = (const int*)d_in[2];   // [B]
    const int*   away       = (const int*)d_in[3];   // [B]
    const float* emb        = (const float*)d_in[4]; // [N, 3]
    float*       out        = (float*)d_out;         // [B, 3]

    const int E = in_sizes[1];
    const int B = in_sizes[2];
    int       N = in_sizes[4] / 3;
    if (N > N_MAX) N = N_MAX;

    const int* row = edge_index;
    const int* col = edge_index + E;

    const int T = 256;
    k_weights<<<1, 64>>>((const float*)d_in[5], (const float*)d_in[6],
                         (const float*)d_in[7], (const float*)d_in[8],
                         (const float*)d_in[9], (const float*)d_in[10]);
    k_init<<<(N + T - 1) / T, T>>>(emb, N);
    k_deg<<<(E + T - 1) / T, T>>>(col, ew, E);
    k_dinv<<<(N + T - 1) / T, T>>>(N);
    k_msg<<<(E + T - 1) / T, T>>>(row, col, ew, E);
    k_node<<<(N + T - 1) / T, T>>>(N);

    const int items_per_block = T * MLP_ITEMS;
    k_mlp<<<(B + items_per_block - 1) / items_per_block, T>>>(home, away, out, B);
    k_sum<<<(B + items_per_block - 1) / items_per_block, T>>>(out, B);
    k_lse<<<1, 32>>>();
    k_final<<<(3 * B + T - 1) / T, T>>>(out, 3 * B);
}

// round 4
// speedup vs baseline: 1.3676x; 1.3676x over previous
#include <cuda_runtime.h>
#include <math.h>

#define N_MAX 1000000

// ---------------- device scratch (no allocation allowed) ----------------
static __device__ float    g_deg[N_MAX];     // weighted in-degree per node
static __device__ float    g_dinv[N_MAX];    // rsqrt(deg)
static __device__ float4   g_x[N_MAX];       // x=emb@w_conv -> premult dinv*x -> conv1 out
static __device__ float4   g_agg[N_MAX];     // unnormalized message accumulator
static __device__ unsigned g_maxu[3];        // column max (order-preserving uint key)
static __device__ float    g_sum[3];         // column sum of exp(h - max)
static __device__ float    g_lse[3];         // final logsumexp per column

// packed weights: [0:9) w_conv, [9:12) b_conv, [12:48) w1, [48:54) b1,
//                 [54:72) w3, [72:75) b3
static __device__ float g_w[80];

__device__ __forceinline__ float lrelu(float x) { return x >= 0.f ? x : 0.01f * x; }

__device__ __forceinline__ unsigned fkey(float x) {
    unsigned u = __float_as_uint(x);
    return (u & 0x80000000u) ? ~u : (u | 0x80000000u);
}
__device__ __forceinline__ float funkey(unsigned k) {
    return __uint_as_float((k & 0x80000000u) ? (k ^ 0x80000000u) : ~k);
}

__device__ __forceinline__ void red_v4(float* p, float a, float b, float c) {
    asm volatile("red.global.add.v4.f32 [%0], {%1, %2, %3, %4};"
                 :: "l"(p), "f"(a), "f"(b), "f"(c), "f"(0.f) : "memory");
}

// ---------------- kernels ----------------

__global__ void k_weights(const float* __restrict__ wconv, const float* __restrict__ bconv,
                          const float* __restrict__ w1, const float* __restrict__ b1,
                          const float* __restrict__ w3, const float* __restrict__ b3) {
    int t = threadIdx.x;
    if (t < 9)  g_w[t]      = wconv[t];
    if (t < 3)  g_w[9 + t]  = bconv[t];
    if (t < 36) g_w[12 + t] = w1[t];
    if (t < 6)  g_w[48 + t] = b1[t];
    if (t < 18) g_w[54 + t] = w3[t];
    if (t < 3)  g_w[72 + t] = b3[t];
    if (t < 3)  { g_maxu[t] = 0u; g_sum[t] = 0.f; }
}

// x = emb @ w_conv; zero deg and agg
__global__ void k_init(const float* __restrict__ emb, int n) {
    int i = blockIdx.x * blockDim.x + threadIdx.x;
    if (i < n) {
        float e0 = emb[3 * i + 0];
        float e1 = emb[3 * i + 1];
        float e2 = emb[3 * i + 2];
        float4 x;
        x.x = e0 * g_w[0] + e1 * g_w[3] + e2 * g_w[6];
        x.y = e0 * g_w[1] + e1 * g_w[4] + e2 * g_w[7];
        x.z = e0 * g_w[2] + e1 * g_w[5] + e2 * g_w[8];
        x.w = 0.f;
        g_x[i] = x;
        g_deg[i] = 0.f;
        g_agg[i] = make_float4(0.f, 0.f, 0.f, 0.f);
    }
}

// weighted in-degree over target nodes (col); 4 edges per thread
__global__ void k_deg(const int4* __restrict__ col4, const float4* __restrict__ ew4,
                      int e4, const int* __restrict__ col, const float* __restrict__ ew, int e) {
    int i = blockIdx.x * blockDim.x + threadIdx.x;
    if (i < e4) {
        int4   c = __ldg(&col4[i]);
        float4 w = __ldg(&ew4[i]);
        atomicAdd(&g_deg[c.x], w.x);
        atomicAdd(&g_deg[c.y], w.y);
        atomicAdd(&g_deg[c.z], w.z);
        atomicAdd(&g_deg[c.w], w.w);
    }
    if (i == 0) {
        for (int j = e4 * 4; j < e; j++) atomicAdd(&g_deg[col[j]], ew[j]);
    }
}

// dinv = rsqrt(deg); premultiply x_pre = dinv * x
__global__ void k_dinv(int n) {
    int i = blockIdx.x * blockDim.x + threadIdx.x;
    if (i < n) {
        float d = g_deg[i];
        float di = d > 0.f ? rsqrtf(d) : 0.f;
        g_dinv[i] = di;
        float4 x = g_x[i];
        x.x *= di; x.y *= di; x.z *= di;
        g_x[i] = x;
    }
}

// agg[col] += ew * x_pre[row]   (2 random sectors per edge: gather + v4 red)
__global__ void k_msg(const int4* __restrict__ row4, const int4* __restrict__ col4,
                      const float4* __restrict__ ew4, int e4,
                      const int* __restrict__ row, const int* __restrict__ col,
                      const float* __restrict__ ew, int e) {
    int i = blockIdx.x * blockDim.x + threadIdx.x;
    if (i < e4) {
        int4   r = __ldg(&row4[i]);
        int4   c = __ldg(&col4[i]);
        float4 w = __ldg(&ew4[i]);
        float4 x0 = g_x[r.x];
        float4 x1 = g_x[r.y];
        float4 x2 = g_x[r.z];
        float4 x3 = g_x[r.w];
        red_v4(reinterpret_cast<float*>(&g_agg[c.x]), w.x * x0.x, w.x * x0.y, w.x * x0.z);
        red_v4(reinterpret_cast<float*>(&g_agg[c.y]), w.y * x1.x, w.y * x1.y, w.y * x1.z);
        red_v4(reinterpret_cast<float*>(&g_agg[c.z]), w.z * x2.x, w.z * x2.y, w.z * x2.z);
        red_v4(reinterpret_cast<float*>(&g_agg[c.w]), w.w * x3.x, w.w * x3.y, w.w * x3.z);
    }
    if (i == 0) {
        for (int j = e4 * 4; j < e; j++) {
            float4 xv = g_x[row[j]];
            float  w  = ew[j];
            red_v4(reinterpret_cast<float*>(&g_agg[col[j]]), w * xv.x, w * xv.y, w * xv.z);
        }
    }
}

// conv1 output: x = leaky_relu(dinv[c]*agg[c] + b_conv)
__global__ void k_node(int n) {
    int i = blockIdx.x * blockDim.x + threadIdx.x;
    if (i < n) {
        float4 a = g_agg[i];
        float  di = g_dinv[i];
        float4 o;
        o.x = lrelu(di * a.x + g_w[9]);
        o.y = lrelu(di * a.y + g_w[10]);
        o.z = lrelu(di * a.z + g_w[11]);
        o.w = 0.f;
        g_x[i] = o;
    }
}

// MLP per batch element + per-block column-max reduction
#define MLP_ITEMS 4
__global__ void k_mlp(const int* __restrict__ home, const int* __restrict__ away,
                      float* __restrict__ out, int b) {
    __shared__ float w[80];
    if (threadIdx.x < 80) w[threadIdx.x] = g_w[threadIdx.x];
    __syncthreads();

    int base = (blockIdx.x * blockDim.x + threadIdx.x) * MLP_ITEMS;
    float m0 = -INFINITY, m1 = -INFINITY, m2 = -INFINITY;
    #pragma unroll
    for (int t = 0; t < MLP_ITEMS; t++) {
        int idx = base + t;
        if (idx < b) {
            float4 xh = g_x[__ldg(&home[idx])];
            float4 xa = g_x[__ldg(&away[idx])];
            float h[6] = {xh.x, xh.y, xh.z, xa.x, xa.y, xa.z};
            float u[6];
            #pragma unroll
            for (int j = 0; j < 6; j++) {
                float s = w[48 + j];
                #pragma unroll
                for (int i2 = 0; i2 < 6; i2++) s += h[i2] * w[12 + i2 * 6 + j];
                u[j] = lrelu(s);
            }
            float o[3];
            #pragma unroll
            for (int j = 0; j < 3; j++) {
                float s = w[72 + j];
                #pragma unroll
                for (int i2 = 0; i2 < 6; i2++) s += u[i2] * w[54 + i2 * 3 + j];
                o[j] = lrelu(s);
            }
            out[3 * idx + 0] = o[0];
            out[3 * idx + 1] = o[1];
            out[3 * idx + 2] = o[2];
            m0 = fmaxf(m0, o[0]);
            m1 = fmaxf(m1, o[1]);
            m2 = fmaxf(m2, o[2]);
        }
    }
    #pragma unroll
    for (int off = 16; off; off >>= 1) {
        m0 = fmaxf(m0, __shfl_xor_sync(0xFFFFFFFFu, m0, off));
        m1 = fmaxf(m1, __shfl_xor_sync(0xFFFFFFFFu, m1, off));
        m2 = fmaxf(m2, __shfl_xor_sync(0xFFFFFFFFu, m2, off));
    }
    __shared__ float sm[3][8];
    int lane = threadIdx.x & 31, wpw = threadIdx.x >> 5;
    if (lane == 0) { sm[0][wpw] = m0; sm[1][wpw] = m1; sm[2][wpw] = m2; }
    __syncthreads();
    if (threadIdx.x < 3) {
        float m = sm[threadIdx.x][0];
        #pragma unroll
        for (int k = 1; k < 8; k++) m = fmaxf(m, sm[threadIdx.x][k]);
        atomicMax(&g_maxu[threadIdx.x], fkey(m));
    }
}

// column sums of exp(h - max)
__global__ void k_sum(const float* __restrict__ out, int b) {
    float M0 = funkey(g_maxu[0]);
    float M1 = funkey(g_maxu[1]);
    float M2 = funkey(g_maxu[2]);
    int base = (blockIdx.x * blockDim.x + threadIdx.x) * MLP_ITEMS;
    float s0 = 0.f, s1 = 0.f, s2 = 0.f;
    #pragma unroll
    for (int t = 0; t < MLP_ITEMS; t++) {
        int idx = base + t;
        if (idx < b) {
            s0 += __expf(out[3 * idx + 0] - M0);
            s1 += __expf(out[3 * idx + 1] - M1);
            s2 += __expf(out[3 * idx + 2] - M2);
        }
    }
    #pragma unroll
    for (int off = 16; off; off >>= 1) {
        s0 += __shfl_xor_sync(0xFFFFFFFFu, s0, off);
        s1 += __shfl_xor_sync(0xFFFFFFFFu, s1, off);
        s2 += __shfl_xor_sync(0xFFFFFFFFu, s2, off);
    }
    __shared__ float sm[3][8];
    int lane = threadIdx.x & 31, w = threadIdx.x >> 5;
    if (lane == 0) { sm[0][w] = s0; sm[1][w] = s1; sm[2][w] = s2; }
    __syncthreads();
    if (threadIdx.x < 3) {
        float s = 0.f;
        #pragma unroll
        for (int k = 0; k < 8; k++) s += sm[threadIdx.x][k];
        atomicAdd(&g_sum[threadIdx.x], s);
    }
}

__global__ void k_lse() {
    int c = threadIdx.x;
    if (c < 3) g_lse[c] = funkey(g_maxu[c]) + logf(g_sum[c]);
}

// out -= lse[col]
__global__ void k_final(float* __restrict__ out, int total) {
    int i = blockIdx.x * blockDim.x + threadIdx.x;
    if (i < total) {
        int c = i - (i / 3) * 3;
        out[i] -= g_lse[c];
    }
}

// ---------------- launch ----------------
extern "C" void kernel_launch(void* const* d_in, const int* in_sizes, int n_in,
                              void* d_out, int out_size) {
    const int*   edge_index = (const int*)d_in[0];   // [2, E]
    const float* ew         = (const float*)d_in[1]; // [E]
    const int*   home       = (const int*)d_in[2];   // [B]
    const int*   away       = (const int*)d_in[3];   // [B]
    const float* emb        = (const float*)d_in[4]; // [N, 3]
    float*       out        = (float*)d_out;         // [B, 3]

    const int E = in_sizes[1];
    const int B = in_sizes[2];
    int       N = in_sizes[4] / 3;
    if (N > N_MAX) N = N_MAX;

    const int* row = edge_index;
    const int* col = edge_index + E;
    const int  E4  = E / 4;

    const int T = 256;
    k_weights<<<1, 64>>>((const float*)d_in[5], (const float*)d_in[6],
                         (const float*)d_in[7], (const float*)d_in[8],
                         (const float*)d_in[9], (const float*)d_in[10]);
    k_init<<<(N + T - 1) / T, T>>>(emb, N);
    k_deg<<<(E4 + T - 1) / T, T>>>((const int4*)col, (const float4*)ew, E4, col, ew, E);
    k_dinv<<<(N + T - 1) / T, T>>>(N);
    k_msg<<<(E4 + T - 1) / T, T>>>((const int4*)row, (const int4*)col,
                                   (const float4*)ew, E4, row, col, ew, E);
    k_node<<<(N + T - 1) / T, T>>>(N);

    const int items_per_block = T * MLP_ITEMS;
    k_mlp<<<(B + items_per_block - 1) / items_per_block, T>>>(home, away, out, B);
    k_sum<<<(B + items_per_block - 1) / items_per_block, T>>>(out, B);
    k_lse<<<1, 32>>>();
    k_final<<<(3 * B + T - 1) / T, T>>>(out, 3 * B);
}

// round 5
// speedup vs baseline: 1.4115x; 1.0321x over previous
#include <cuda_runtime.h>
#include <math.h>

#define N_MAX 1000000
#define PART_MAX 4096

// ---------------- device scratch (no allocation allowed) ----------------
static __device__ float    g_deg[N_MAX];     // weighted in-degree per node
static __device__ float    g_dinv[N_MAX];    // rsqrt(deg)
static __device__ float4   g_x[N_MAX];       // x=emb@w_conv -> premult dinv*x -> conv1 out
static __device__ float4   g_agg[N_MAX];     // unnormalized message accumulator
static __device__ float    g_pmax[3 * PART_MAX]; // per-block column max
static __device__ float    g_psum[3 * PART_MAX]; // per-block sum exp(o - blockmax)
static __device__ float    g_lse[3];         // final logsumexp per column

// packed weights: [0:9) w_conv, [9:12) b_conv, [12:48) w1, [48:54) b1,
//                 [54:72) w3, [72:75) b3
static __device__ float g_w[80];

__device__ __forceinline__ float lrelu(float x) { return x >= 0.f ? x : 0.01f * x; }

__device__ __forceinline__ void red_v4(float* p, float a, float b, float c) {
    asm volatile("red.global.add.v4.f32 [%0], {%1, %2, %3, %4};"
                 :: "l"(p), "f"(a), "f"(b), "f"(c), "f"(0.f) : "memory");
}

// ---------------- kernels ----------------

// zero deg (runs on main stream ahead of k_deg)
__global__ void k_zero(int n) {
    int i = blockIdx.x * blockDim.x + threadIdx.x;
    if (i < n) g_deg[i] = 0.f;
}

__global__ void k_weights(const float* __restrict__ wconv, const float* __restrict__ bconv,
                          const float* __restrict__ w1, const float* __restrict__ b1,
                          const float* __restrict__ w3, const float* __restrict__ b3) {
    int t = threadIdx.x;
    if (t < 9)  g_w[t]      = wconv[t];
    if (t < 3)  g_w[9 + t]  = bconv[t];
    if (t < 36) g_w[12 + t] = w1[t];
    if (t < 6)  g_w[48 + t] = b1[t];
    if (t < 18) g_w[54 + t] = w3[t];
    if (t < 3)  g_w[72 + t] = b3[t];
}

// x = emb @ w_conv; zero agg   (forked stream, overlaps k_deg)
__global__ void k_initx(const float* __restrict__ emb, int n) {
    int i = blockIdx.x * blockDim.x + threadIdx.x;
    if (i < n) {
        float e0 = emb[3 * i + 0];
        float e1 = emb[3 * i + 1];
        float e2 = emb[3 * i + 2];
        float4 x;
        x.x = e0 * g_w[0] + e1 * g_w[3] + e2 * g_w[6];
        x.y = e0 * g_w[1] + e1 * g_w[4] + e2 * g_w[7];
        x.z = e0 * g_w[2] + e1 * g_w[5] + e2 * g_w[8];
        x.w = 0.f;
        g_x[i] = x;
        g_agg[i] = make_float4(0.f, 0.f, 0.f, 0.f);
    }
}

// weighted in-degree over target nodes (col); 4 edges per thread
__global__ void k_deg(const int4* __restrict__ col4, const float4* __restrict__ ew4,
                      int e4, const int* __restrict__ col, const float* __restrict__ ew, int e) {
    int i = blockIdx.x * blockDim.x + threadIdx.x;
    if (i < e4) {
        int4   c = __ldg(&col4[i]);
        float4 w = __ldg(&ew4[i]);
        atomicAdd(&g_deg[c.x], w.x);
        atomicAdd(&g_deg[c.y], w.y);
        atomicAdd(&g_deg[c.z], w.z);
        atomicAdd(&g_deg[c.w], w.w);
    }
    if (i == 0) {
        for (int j = e4 * 4; j < e; j++) atomicAdd(&g_deg[col[j]], ew[j]);
    }
}

// dinv = rsqrt(deg); premultiply x_pre = dinv * x
__global__ void k_dinv(int n) {
    int i = blockIdx.x * blockDim.x + threadIdx.x;
    if (i < n) {
        float d = g_deg[i];
        float di = d > 0.f ? rsqrtf(d) : 0.f;
        g_dinv[i] = di;
        float4 x = g_x[i];
        x.x *= di; x.y *= di; x.z *= di;
        g_x[i] = x;
    }
}

// agg[col] += ew * x_pre[row]   (2 random sectors per edge: gather + v4 red)
__global__ void k_msg(const int4* __restrict__ row4, const int4* __restrict__ col4,
                      const float4* __restrict__ ew4, int e4,
                      const int* __restrict__ row, const int* __restrict__ col,
                      const float* __restrict__ ew, int e) {
    int i = blockIdx.x * blockDim.x + threadIdx.x;
    if (i < e4) {
        int4   r = __ldg(&row4[i]);
        int4   c = __ldg(&col4[i]);
        float4 w = __ldg(&ew4[i]);
        float4 x0 = g_x[r.x];
        float4 x1 = g_x[r.y];
        float4 x2 = g_x[r.z];
        float4 x3 = g_x[r.w];
        red_v4(reinterpret_cast<float*>(&g_agg[c.x]), w.x * x0.x, w.x * x0.y, w.x * x0.z);
        red_v4(reinterpret_cast<float*>(&g_agg[c.y]), w.y * x1.x, w.y * x1.y, w.y * x1.z);
        red_v4(reinterpret_cast<float*>(&g_agg[c.z]), w.z * x2.x, w.z * x2.y, w.z * x2.z);
        red_v4(reinterpret_cast<float*>(&g_agg[c.w]), w.w * x3.x, w.w * x3.y, w.w * x3.z);
    }
    if (i == 0) {
        for (int j = e4 * 4; j < e; j++) {
            float4 xv = g_x[row[j]];
            float  w  = ew[j];
            red_v4(reinterpret_cast<float*>(&g_agg[col[j]]), w * xv.x, w * xv.y, w * xv.z);
        }
    }
}

// conv1 output: x = leaky_relu(dinv[c]*agg[c] + b_conv)
__global__ void k_node(int n) {
    int i = blockIdx.x * blockDim.x + threadIdx.x;
    if (i < n) {
        float4 a = g_agg[i];
        float  di = g_dinv[i];
        float4 o;
        o.x = lrelu(di * a.x + g_w[9]);
        o.y = lrelu(di * a.y + g_w[10]);
        o.z = lrelu(di * a.z + g_w[11]);
        o.w = 0.f;
        g_x[i] = o;
    }
}

// MLP per batch element; emits out + per-block (max, sum exp(o - max)) partials
#define MLP_ITEMS 4
__global__ void k_mlp(const int* __restrict__ home, const int* __restrict__ away,
                      float* __restrict__ out, int b) {
    __shared__ float w[80];
    if (threadIdx.x < 80) w[threadIdx.x] = g_w[threadIdx.x];
    __syncthreads();

    int base = (blockIdx.x * blockDim.x + threadIdx.x) * MLP_ITEMS;
    float o[MLP_ITEMS][3];
    int   nval = 0;
    float m0 = -INFINITY, m1 = -INFINITY, m2 = -INFINITY;
    #pragma unroll
    for (int t = 0; t < MLP_ITEMS; t++) {
        int idx = base + t;
        if (idx < b) {
            float4 xh = g_x[__ldg(&home[idx])];
            float4 xa = g_x[__ldg(&away[idx])];
            float h[6] = {xh.x, xh.y, xh.z, xa.x, xa.y, xa.z};
            float u[6];
            #pragma unroll
            for (int j = 0; j < 6; j++) {
                float s = w[48 + j];
                #pragma unroll
                for (int i2 = 0; i2 < 6; i2++) s += h[i2] * w[12 + i2 * 6 + j];
                u[j] = lrelu(s);
            }
            #pragma unroll
            for (int j = 0; j < 3; j++) {
                float s = w[72 + j];
                #pragma unroll
                for (int i2 = 0; i2 < 6; i2++) s += u[i2] * w[54 + i2 * 3 + j];
                o[t][j] = lrelu(s);
            }
            out[3 * idx + 0] = o[t][0];
            out[3 * idx + 1] = o[t][1];
            out[3 * idx + 2] = o[t][2];
            m0 = fmaxf(m0, o[t][0]);
            m1 = fmaxf(m1, o[t][1]);
            m2 = fmaxf(m2, o[t][2]);
            nval = t + 1;
        }
    }
    // block max reduction
    #pragma unroll
    for (int off = 16; off; off >>= 1) {
        m0 = fmaxf(m0, __shfl_xor_sync(0xFFFFFFFFu, m0, off));
        m1 = fmaxf(m1, __shfl_xor_sync(0xFFFFFFFFu, m1, off));
        m2 = fmaxf(m2, __shfl_xor_sync(0xFFFFFFFFu, m2, off));
    }
    __shared__ float sm[3][8];
    int lane = threadIdx.x & 31, wpw = threadIdx.x >> 5;
    if (lane == 0) { sm[0][wpw] = m0; sm[1][wpw] = m1; sm[2][wpw] = m2; }
    __syncthreads();
    float M0 = sm[0][0], M1 = sm[1][0], M2 = sm[2][0];
    #pragma unroll
    for (int k = 1; k < 8; k++) {
        M0 = fmaxf(M0, sm[0][k]); M1 = fmaxf(M1, sm[1][k]); M2 = fmaxf(M2, sm[2][k]);
    }
    // block sums of exp(o - blockmax) from registers
    float s0 = 0.f, s1 = 0.f, s2 = 0.f;
    #pragma unroll
    for (int t = 0; t < MLP_ITEMS; t++) {
        if (t < nval) {
            s0 += __expf(o[t][0] - M0);
            s1 += __expf(o[t][1] - M1);
            s2 += __expf(o[t][2] - M2);
        }
    }
    #pragma unroll
    for (int off = 16; off; off >>= 1) {
        s0 += __shfl_xor_sync(0xFFFFFFFFu, s0, off);
        s1 += __shfl_xor_sync(0xFFFFFFFFu, s1, off);
        s2 += __shfl_xor_sync(0xFFFFFFFFu, s2, off);
    }
    __syncthreads();
    if (lane == 0) { sm[0][wpw] = s0; sm[1][wpw] = s1; sm[2][wpw] = s2; }
    __syncthreads();
    if (threadIdx.x == 0) {
        float t0 = 0.f, t1 = 0.f, t2 = 0.f;
        #pragma unroll
        for (int k = 0; k < 8; k++) { t0 += sm[0][k]; t1 += sm[1][k]; t2 += sm[2][k]; }
        int bb = blockIdx.x;
        g_pmax[0 * PART_MAX + bb] = M0;
        g_pmax[1 * PART_MAX + bb] = M1;
        g_pmax[2 * PART_MAX + bb] = M2;
        g_psum[0 * PART_MAX + bb] = t0;
        g_psum[1 * PART_MAX + bb] = t1;
        g_psum[2 * PART_MAX + bb] = t2;
    }
}

// merge per-block partials -> lse per column (single block)
__global__ void k_merge(int nb) {
    __shared__ float sred[32];
    int t = threadIdx.x;          // 1024 threads
    int lane = t & 31, wpw = t >> 5;
    for (int c = 0; c < 3; c++) {
        float m = (t < nb) ? g_pmax[c * PART_MAX + t] : -INFINITY;
        float mw = m;
        #pragma unroll
        for (int off = 16; off; off >>= 1) mw = fmaxf(mw, __shfl_xor_sync(0xFFFFFFFFu, mw, off));
        if (lane == 0) sred[wpw] = mw;
        __syncthreads();
        float M = sred[0];
        #pragma unroll
        for (int k = 1; k < 32; k++) M = fmaxf(M, sred[k]);
        __syncthreads();
        float s = (t < nb) ? g_psum[c * PART_MAX + t] * __expf(m - M) : 0.f;
        #pragma unroll
        for (int off = 16; off; off >>= 1) s += __shfl_xor_sync(0xFFFFFFFFu, s, off);
        if (lane == 0) sred[wpw] = s;
        __syncthreads();
        if (t == 0) {
            float S = 0.f;
            #pragma unroll
            for (int k = 0; k < 32; k++) S += sred[k];
            g_lse[c] = M + logf(S);
        }
        __syncthreads();
    }
}

// out -= lse[col], vectorized float4 (4 elems/thread) + scalar tail
__global__ void k_final(float4* __restrict__ out4, int nvec, float* __restrict__ out, int total) {
    float l0 = g_lse[0], l1 = g_lse[1], l2 = g_lse[2];
    int v = blockIdx.x * blockDim.x + threadIdx.x;
    if (v < nvec) {
        float4 o = out4[v];
        int m = (v * 4) % 3;           // channel of first element
        float la, lb, lc2;
        if (m == 0)      { la = l0; lb = l1; lc2 = l2; }
        else if (m == 1) { la = l1; lb = l2; lc2 = l0; }
        else             { la = l2; lb = l0; lc2 = l1; }
        o.x -= la; o.y -= lb; o.z -= lc2; o.w -= la;
        out4[v] = o;
    }
    if (v == 0) {
        for (int j = nvec * 4; j < total; j++) out[j] -= g_lse[j % 3];
    }
}

// ---------------- launch ----------------
extern "C" void kernel_launch(void* const* d_in, const int* in_sizes, int n_in,
                              void* d_out, int out_size) {
    const int*   edge_index = (const int*)d_in[0];   // [2, E]
    const float* ew         = (const float*)d_in[1]; // [E]
    const int*   home       = (const int*)d_in[2];   // [B]
    const int*   away       = (const int*)d_in[3];   // [B]
    const float* emb        = (const float*)d_in[4]; // [N, 3]
    float*       out        = (float*)d_out;         // [B, 3]

    const int E = in_sizes[1];
    const int B = in_sizes[2];
    int       N = in_sizes[4] / 3;
    if (N > N_MAX) N = N_MAX;

    const int* row = edge_index;
    const int* col = edge_index + E;
    const int  E4  = E / 4;

    // fork/join: side stream does weights + x-transform while main does deg atomics
    cudaStream_t s1;
    cudaStreamCreateWithFlags(&s1, cudaStreamNonBlocking);
    cudaEvent_t eFork, eJoin;
    cudaEventCreateWithFlags(&eFork, cudaEventDisableTiming);
    cudaEventCreateWithFlags(&eJoin, cudaEventDisableTiming);

    const int T = 256;
    k_zero<<<(N + T - 1) / T, T>>>(N);
    cudaEventRecord(eFork, 0);
    cudaStreamWaitEvent(s1, eFork, 0);

    // side stream
    k_weights<<<1, 64, 0, s1>>>((const float*)d_in[5], (const float*)d_in[6],
                                (const float*)d_in[7], (const float*)d_in[8],
                                (const float*)d_in[9], (const float*)d_in[10]);
    k_initx<<<(N + T - 1) / T, T, 0, s1>>>(emb, N);
    cudaEventRecord(eJoin, s1);

    // main stream (concurrent with side stream)
    k_deg<<<(E4 + T - 1) / T, T>>>((const int4*)col, (const float4*)ew, E4, col, ew, E);

    cudaStreamWaitEvent(0, eJoin, 0);   // join

    k_dinv<<<(N + T - 1) / T, T>>>(N);
    k_msg<<<(E4 + T - 1) / T, T>>>((const int4*)row, (const int4*)col,
                                   (const float4*)ew, E4, row, col, ew, E);
    k_node<<<(N + T - 1) / T, T>>>(N);

    const int items_per_block = T * MLP_ITEMS;
    const int nb = (B + items_per_block - 1) / items_per_block;
    k_mlp<<<nb, T>>>(home, away, out, B);
    k_merge<<<1, 1024>>>(nb);
    const int total = 3 * B;
    const int nvec  = total / 4;
    k_final<<<(nvec + T - 1) / T, T>>>((float4*)out, nvec, out, total);
}

// round 6
// speedup vs baseline: 1.4348x; 1.0165x over previous
#include <cuda_runtime.h>
#include <math.h>

#define N_MAX 1000000
#define PART_MAX 4096

// ---------------- device scratch (no allocation allowed) ----------------
static __device__ float    g_deg[N_MAX];     // weighted in-degree (zero at entry, re-zeroed post-use)
static __device__ float    g_dinv[N_MAX];    // rsqrt(deg)
static __device__ float4   g_x[N_MAX];       // x=emb@w_conv -> premult dinv*x -> conv1 out
static __device__ float4   g_agg[N_MAX];     // unnormalized message accumulator
static __device__ float    g_pmax[3 * PART_MAX]; // per-block column max
static __device__ float    g_psum[3 * PART_MAX]; // per-block sum exp(o - blockmax)
static __device__ float    g_lse[3];         // final logsumexp per column

// packed weights: [0:9) w_conv, [9:12) b_conv, [12:48) w1, [48:54) b1,
//                 [54:72) w3, [72:75) b3
static __device__ float g_w[80];

__device__ __forceinline__ float lrelu(float x) { return x >= 0.f ? x : 0.01f * x; }

__device__ __forceinline__ void red_v4(float* p, float a, float b, float c) {
    asm volatile("red.global.add.v4.f32 [%0], {%1, %2, %3, %4};"
                 :: "l"(p), "f"(a), "f"(b), "f"(c), "f"(0.f) : "memory");
}

// ---------------- kernels ----------------

__global__ void k_weights(const float* __restrict__ wconv, const float* __restrict__ bconv,
                          const float* __restrict__ w1, const float* __restrict__ b1,
                          const float* __restrict__ w3, const float* __restrict__ b3) {
    int t = threadIdx.x;
    if (t < 9)  g_w[t]      = wconv[t];
    if (t < 3)  g_w[9 + t]  = bconv[t];
    if (t < 36) g_w[12 + t] = w1[t];
    if (t < 6)  g_w[48 + t] = b1[t];
    if (t < 18) g_w[54 + t] = w3[t];
    if (t < 3)  g_w[72 + t] = b3[t];
}

// x = emb @ w_conv; zero agg   (side stream, overlaps k_deg)
__global__ void k_initx(const float* __restrict__ emb, int n) {
    int i = blockIdx.x * blockDim.x + threadIdx.x;
    if (i < n) {
        float e0 = emb[3 * i + 0];
        float e1 = emb[3 * i + 1];
        float e2 = emb[3 * i + 2];
        float4 x;
        x.x = e0 * g_w[0] + e1 * g_w[3] + e2 * g_w[6];
        x.y = e0 * g_w[1] + e1 * g_w[4] + e2 * g_w[7];
        x.z = e0 * g_w[2] + e1 * g_w[5] + e2 * g_w[8];
        x.w = 0.f;
        g_x[i] = x;
        g_agg[i] = make_float4(0.f, 0.f, 0.f, 0.f);
    }
}

// weighted in-degree over target nodes (col); 4 edges per thread
// PRECONDITION: g_deg == 0 (BSS-zero on first call; k_zerodeg restores per call)
__global__ void k_deg(const int4* __restrict__ col4, const float4* __restrict__ ew4,
                      int e4, const int* __restrict__ col, const float* __restrict__ ew, int e) {
    int i = blockIdx.x * blockDim.x + threadIdx.x;
    if (i < e4) {
        int4   c = __ldg(&col4[i]);
        float4 w = __ldg(&ew4[i]);
        atomicAdd(&g_deg[c.x], w.x);
        atomicAdd(&g_deg[c.y], w.y);
        atomicAdd(&g_deg[c.z], w.z);
        atomicAdd(&g_deg[c.w], w.w);
    }
    if (i == 0) {
        for (int j = e4 * 4; j < e; j++) atomicAdd(&g_deg[col[j]], ew[j]);
    }
}

// dinv = rsqrt(deg); premultiply x_pre = dinv * x
__global__ void k_dinv(int n) {
    int i = blockIdx.x * blockDim.x + threadIdx.x;
    if (i < n) {
        float d = g_deg[i];
        float di = d > 0.f ? rsqrtf(d) : 0.f;
        g_dinv[i] = di;
        float4 x = g_x[i];
        x.x *= di; x.y *= di; x.z *= di;
        g_x[i] = x;
    }
}

// re-zero deg for the next call/replay (side stream, overlaps k_msg)
__global__ void k_zerodeg(int n) {
    int i = blockIdx.x * blockDim.x + threadIdx.x;
    if (i < n) g_deg[i] = 0.f;
}

// agg[col] += ew * x_pre[row]   (2 random sectors per edge: gather + v4 red)
__global__ void k_msg(const int4* __restrict__ row4, const int4* __restrict__ col4,
                      const float4* __restrict__ ew4, int e4,
                      const int* __restrict__ row, const int* __restrict__ col,
                      const float* __restrict__ ew, int e) {
    int i = blockIdx.x * blockDim.x + threadIdx.x;
    if (i < e4) {
        int4   r = __ldg(&row4[i]);
        int4   c = __ldg(&col4[i]);
        float4 w = __ldg(&ew4[i]);
        float4 x0 = g_x[r.x];
        float4 x1 = g_x[r.y];
        float4 x2 = g_x[r.z];
        float4 x3 = g_x[r.w];
        red_v4(reinterpret_cast<float*>(&g_agg[c.x]), w.x * x0.x, w.x * x0.y, w.x * x0.z);
        red_v4(reinterpret_cast<float*>(&g_agg[c.y]), w.y * x1.x, w.y * x1.y, w.y * x1.z);
        red_v4(reinterpret_cast<float*>(&g_agg[c.z]), w.z * x2.x, w.z * x2.y, w.z * x2.z);
        red_v4(reinterpret_cast<float*>(&g_agg[c.w]), w.w * x3.x, w.w * x3.y, w.w * x3.z);
    }
    if (i == 0) {
        for (int j = e4 * 4; j < e; j++) {
            float4 xv = g_x[row[j]];
            float  w  = ew[j];
            red_v4(reinterpret_cast<float*>(&g_agg[col[j]]), w * xv.x, w * xv.y, w * xv.z);
        }
    }
}

// conv1 output: x = leaky_relu(dinv[c]*agg[c] + b_conv)
__global__ void k_node(int n) {
    int i = blockIdx.x * blockDim.x + threadIdx.x;
    if (i < n) {
        float4 a = g_agg[i];
        float  di = g_dinv[i];
        float4 o;
        o.x = lrelu(di * a.x + g_w[9]);
        o.y = lrelu(di * a.y + g_w[10]);
        o.z = lrelu(di * a.z + g_w[11]);
        o.w = 0.f;
        g_x[i] = o;
    }
}

// MLP per batch element; emits out + per-block (max, sum exp(o - max)) partials
// 8 items/thread; int4 index loads, float4 output stores
#define MLP_ITEMS 8
__global__ void k_mlp(const int4* __restrict__ home4, const int4* __restrict__ away4,
                      float4* __restrict__ out4, int b) {
    __shared__ float w[80];
    if (threadIdx.x < 80) w[threadIdx.x] = g_w[threadIdx.x];
    __syncthreads();

    int tid  = blockIdx.x * blockDim.x + threadIdx.x;
    int base = tid * MLP_ITEMS;            // item index; base*3 divisible by 4
    float o[MLP_ITEMS][3];
    int   nval = 0;
    float m0 = -INFINITY, m1 = -INFINITY, m2 = -INFINITY;

    if (base + MLP_ITEMS <= b) {
        int4 h0 = __ldg(&home4[tid * 2]);
        int4 h1 = __ldg(&home4[tid * 2 + 1]);
        int4 a0 = __ldg(&away4[tid * 2]);
        int4 a1 = __ldg(&away4[tid * 2 + 1]);
        int hi[8] = {h0.x, h0.y, h0.z, h0.w, h1.x, h1.y, h1.z, h1.w};
        int ai[8] = {a0.x, a0.y, a0.z, a0.w, a1.x, a1.y, a1.z, a1.w};
        #pragma unroll
        for (int t = 0; t < MLP_ITEMS; t++) {
            float4 xh = g_x[hi[t]];
            float4 xa = g_x[ai[t]];
            float h[6] = {xh.x, xh.y, xh.z, xa.x, xa.y, xa.z};
            float u[6];
            #pragma unroll
            for (int j = 0; j < 6; j++) {
                float s = w[48 + j];
                #pragma unroll
                for (int i2 = 0; i2 < 6; i2++) s += h[i2] * w[12 + i2 * 6 + j];
                u[j] = lrelu(s);
            }
            #pragma unroll
            for (int j = 0; j < 3; j++) {
                float s = w[72 + j];
                #pragma unroll
                for (int i2 = 0; i2 < 6; i2++) s += u[i2] * w[54 + i2 * 3 + j];
                o[t][j] = lrelu(s);
            }
            m0 = fmaxf(m0, o[t][0]);
            m1 = fmaxf(m1, o[t][1]);
            m2 = fmaxf(m2, o[t][2]);
        }
        nval = MLP_ITEMS;
        // 24 contiguous floats -> 6 float4 stores
        const float* of = &o[0][0];
        int vbase = (base * 3) / 4;
        #pragma unroll
        for (int v = 0; v < 6; v++)
            out4[vbase + v] = make_float4(of[4 * v], of[4 * v + 1], of[4 * v + 2], of[4 * v + 3]);
    } else {
        // tail: scalar path
        const int* home = (const int*)home4;
        const int* away = (const int*)away4;
        float* out = (float*)out4;
        #pragma unroll
        for (int t = 0; t < MLP_ITEMS; t++) {
            int idx = base + t;
            if (idx < b) {
                float4 xh = g_x[__ldg(&home[idx])];
                float4 xa = g_x[__ldg(&away[idx])];
                float h[6] = {xh.x, xh.y, xh.z, xa.x, xa.y, xa.z};
                float u[6];
                #pragma unroll
                for (int j = 0; j < 6; j++) {
                    float s = w[48 + j];
                    #pragma unroll
                    for (int i2 = 0; i2 < 6; i2++) s += h[i2] * w[12 + i2 * 6 + j];
                    u[j] = lrelu(s);
                }
                #pragma unroll
                for (int j = 0; j < 3; j++) {
                    float s = w[72 + j];
                    #pragma unroll
                    for (int i2 = 0; i2 < 6; i2++) s += u[i2] * w[54 + i2 * 3 + j];
                    o[t][j] = lrelu(s);
                }
                out[3 * idx + 0] = o[t][0];
                out[3 * idx + 1] = o[t][1];
                out[3 * idx + 2] = o[t][2];
                m0 = fmaxf(m0, o[t][0]);
                m1 = fmaxf(m1, o[t][1]);
                m2 = fmaxf(m2, o[t][2]);
                nval = t + 1;
            }
        }
    }

    // block max reduction
    #pragma unroll
    for (int off = 16; off; off >>= 1) {
        m0 = fmaxf(m0, __shfl_xor_sync(0xFFFFFFFFu, m0, off));
        m1 = fmaxf(m1, __shfl_xor_sync(0xFFFFFFFFu, m1, off));
        m2 = fmaxf(m2, __shfl_xor_sync(0xFFFFFFFFu, m2, off));
    }
    __shared__ float sm[3][8];
    int lane = threadIdx.x & 31, wpw = threadIdx.x >> 5;
    if (lane == 0) { sm[0][wpw] = m0; sm[1][wpw] = m1; sm[2][wpw] = m2; }
    __syncthreads();
    float M0 = sm[0][0], M1 = sm[1][0], M2 = sm[2][0];
    #pragma unroll
    for (int k = 1; k < 8; k++) {
        M0 = fmaxf(M0, sm[0][k]); M1 = fmaxf(M1, sm[1][k]); M2 = fmaxf(M2, sm[2][k]);
    }
    // block sums of exp(o - blockmax) from registers
    float s0 = 0.f, s1 = 0.f, s2 = 0.f;
    #pragma unroll
    for (int t = 0; t < MLP_ITEMS; t++) {
        if (t < nval) {
            s0 += __expf(o[t][0] - M0);
            s1 += __expf(o[t][1] - M1);
            s2 += __expf(o[t][2] - M2);
        }
    }
    #pragma unroll
    for (int off = 16; off; off >>= 1) {
        s0 += __shfl_xor_sync(0xFFFFFFFFu, s0, off);
        s1 += __shfl_xor_sync(0xFFFFFFFFu, s1, off);
        s2 += __shfl_xor_sync(0xFFFFFFFFu, s2, off);
    }
    __syncthreads();
    if (lane == 0) { sm[0][wpw] = s0; sm[1][wpw] = s1; sm[2][wpw] = s2; }
    __syncthreads();
    if (threadIdx.x == 0) {
        float t0 = 0.f, t1 = 0.f, t2 = 0.f;
        #pragma unroll
        for (int k = 0; k < 8; k++) { t0 += sm[0][k]; t1 += sm[1][k]; t2 += sm[2][k]; }
        int bb = blockIdx.x;
        g_pmax[0 * PART_MAX + bb] = M0;
        g_pmax[1 * PART_MAX + bb] = M1;
        g_pmax[2 * PART_MAX + bb] = M2;
        g_psum[0 * PART_MAX + bb] = t0;
        g_psum[1 * PART_MAX + bb] = t1;
        g_psum[2 * PART_MAX + bb] = t2;
    }
}

// merge per-block partials -> lse per column (single block)
__global__ void k_merge(int nb) {
    __shared__ float sred[32];
    int t = threadIdx.x;          // 1024 threads
    int lane = t & 31, wpw = t >> 5;
    for (int c = 0; c < 3; c++) {
        float m = (t < nb) ? g_pmax[c * PART_MAX + t] : -INFINITY;
        float mw = m;
        #pragma unroll
        for (int off = 16; off; off >>= 1) mw = fmaxf(mw, __shfl_xor_sync(0xFFFFFFFFu, mw, off));
        if (lane == 0) sred[wpw] = mw;
        __syncthreads();
        float M = sred[0];
        #pragma unroll
        for (int k = 1; k < 32; k++) M = fmaxf(M, sred[k]);
        __syncthreads();
        float s = (t < nb) ? g_psum[c * PART_MAX + t] * __expf(m - M) : 0.f;
        #pragma unroll
        for (int off = 16; off; off >>= 1) s += __shfl_xor_sync(0xFFFFFFFFu, s, off);
        if (lane == 0) sred[wpw] = s;
        __syncthreads();
        if (t == 0) {
            float S = 0.f;
            #pragma unroll
            for (int k = 0; k < 32; k++) S += sred[k];
            g_lse[c] = M + logf(S);
        }
        __syncthreads();
    }
}

// out -= lse[col], vectorized float4 (4 elems/thread) + scalar tail
__global__ void k_final(float4* __restrict__ out4, int nvec, float* __restrict__ out, int total) {
    float l0 = g_lse[0], l1 = g_lse[1], l2 = g_lse[2];
    int v = blockIdx.x * blockDim.x + threadIdx.x;
    if (v < nvec) {
        float4 o = out4[v];
        int m = (v * 4) % 3;           // channel of first element
        float la, lb, lc2;
        if (m == 0)      { la = l0; lb = l1; lc2 = l2; }
        else if (m == 1) { la = l1; lb = l2; lc2 = l0; }
        else             { la = l2; lb = l0; lc2 = l1; }
        o.x -= la; o.y -= lb; o.z -= lc2; o.w -= la;
        out4[v] = o;
    }
    if (v == 0) {
        for (int j = nvec * 4; j < total; j++) out[j] -= g_lse[j % 3];
    }
}

// ---------------- launch ----------------
extern "C" void kernel_launch(void* const* d_in, const int* in_sizes, int n_in,
                              void* d_out, int out_size) {
    const int*   edge_index = (const int*)d_in[0];   // [2, E]
    const float* ew         = (const float*)d_in[1]; // [E]
    const int*   home       = (const int*)d_in[2];   // [B]
    const int*   away       = (const int*)d_in[3];   // [B]
    const float* emb        = (const float*)d_in[4]; // [N, 3]
    float*       out        = (float*)d_out;         // [B, 3]

    const int E = in_sizes[1];
    const int B = in_sizes[2];
    int       N = in_sizes[4] / 3;
    if (N > N_MAX) N = N_MAX;

    const int* row = edge_index;
    const int* col = edge_index + E;
    const int  E4  = E / 4;

    cudaStream_t s1;
    cudaStreamCreateWithFlags(&s1, cudaStreamNonBlocking);
    cudaEvent_t eFork, eJoin, eFork2, eJoin2;
    cudaEventCreateWithFlags(&eFork, cudaEventDisableTiming);
    cudaEventCreateWithFlags(&eJoin, cudaEventDisableTiming);
    cudaEventCreateWithFlags(&eFork2, cudaEventDisableTiming);
    cudaEventCreateWithFlags(&eJoin2, cudaEventDisableTiming);

    const int T = 256;

    // fork immediately: side does weights + x/agg init while main does deg atomics
    cudaEventRecord(eFork, 0);
    cudaStreamWaitEvent(s1, eFork, 0);
    k_weights<<<1, 64, 0, s1>>>((const float*)d_in[5], (const float*)d_in[6],
                                (const float*)d_in[7], (const float*)d_in[8],
                                (const float*)d_in[9], (const float*)d_in[10]);
    k_initx<<<(N + T - 1) / T, T, 0, s1>>>(emb, N);
    cudaEventRecord(eJoin, s1);

    // main: deg atomics start at t=0 (g_deg==0 invariant)
    k_deg<<<(E4 + T - 1) / T, T>>>((const int4*)col, (const float4*)ew, E4, col, ew, E);

    cudaStreamWaitEvent(0, eJoin, 0);   // join side work

    k_dinv<<<(N + T - 1) / T, T>>>(N);

    // side: re-zero deg for next call, overlapped under k_msg
    cudaEventRecord(eFork2, 0);
    cudaStreamWaitEvent(s1, eFork2, 0);
    k_zerodeg<<<(N + T - 1) / T, T, 0, s1>>>(N);
    cudaEventRecord(eJoin2, s1);

    k_msg<<<(E4 + T - 1) / T, T>>>((const int4*)row, (const int4*)col,
                                   (const float4*)ew, E4, row, col, ew, E);
    k_node<<<(N + T - 1) / T, T>>>(N);

    const int items_per_block = T * MLP_ITEMS;
    const int nb = (B + items_per_block - 1) / items_per_block;
    k_mlp<<<nb, T>>>((const int4*)home, (const int4*)away, (float4*)out, B);
    k_merge<<<1, 1024>>>(nb);

    cudaStreamWaitEvent(0, eJoin2, 0);  // join deg re-zero before graph end

    const int total = 3 * B;
    const int nvec  = total / 4;
    k_final<<<(nvec + T - 1) / T, T>>>((float4*)out, nvec, out, total);
}